// round 1
// baseline (speedup 1.0000x reference)
#include <cuda_runtime.h>

#define NN 100000
#define NE 800000
#define NG 512
#define IND 16
#define HID 64
#define MH  32
#define NL  3
#define EPSB 1e-5f

#define GRID_P 1184   // 8 blocks per SM (148 SMs)

// ------------------- scratch (static device memory; no allocs) -------------------
__device__ float g_h[NN*HID];
__device__ float g_Pa[NN*MH];
__device__ float g_Pb[NN*MH];
__device__ float g_nsum[NN*HID];
__device__ float g_z3[NN*MH];
__device__ float g_y4[NN*HID];
__device__ float g_deg[NN];
__device__ float g_stats[128];     // [0..63] sum per channel, [64..127] sumsq
__device__ float g_c1[128];        // a in [0..63], c in [64..127]
__device__ float g_c2[128];
__device__ float g_c3[128];
__device__ float g_c4[128];        // fold constants for residual (BN4)
__device__ float g_pool[NG*HID];
__device__ float g_pcnt[NG];

// ------------------- prep: zero deg/pool/pcnt/stats -------------------
__global__ void k_prep() {
    int i = blockIdx.x*blockDim.x + threadIdx.x;
    if (i < NN)        g_deg[i]  = 0.f;
    if (i < NG*HID)    g_pool[i] = 0.f;
    if (i < NG)        g_pcnt[i] = 0.f;
    if (i < 128)       g_stats[i] = 0.f;
}

__global__ void k_deg(const int* __restrict__ ei) {
    int e = blockIdx.x*blockDim.x + threadIdx.x;
    if (e < NE) atomicAdd(&g_deg[ei[NE + e]], 1.0f);
}

__global__ void k_zero_nsum() {
    int i = blockIdx.x*blockDim.x + threadIdx.x;   // NN*HID/4 float4
    if (i < NN*HID/4) reinterpret_cast<float4*>(g_nsum)[i] = make_float4(0.f,0.f,0.f,0.f);
}

// ------------------- input projection: h = x @ Win + b -------------------
__global__ __launch_bounds__(256) void k_init(const float* __restrict__ x,
                                              const float* __restrict__ w,
                                              const float* __restrict__ b) {
    __shared__ float Ws[IND*HID];
    __shared__ float bs[HID];
    __shared__ float xs[4][IND];
    int t = threadIdx.x;
    for (int i = t; i < IND*HID; i += 256) Ws[i] = w[i];
    if (t < HID) bs[t] = b[t];
    int ni = t >> 6, c = t & 63;
    for (int node0 = blockIdx.x*4; node0 < NN; node0 += gridDim.x*4) {
        if (t < 4*IND) xs[t/IND][t%IND] = x[(node0 + t/IND)*IND + (t%IND)];
        __syncthreads();
        int n = node0 + ni;
        float acc = bs[c];
        #pragma unroll
        for (int k = 0; k < IND; k++) acc = fmaf(xs[ni][k], Ws[k*HID + c], acc);
        g_h[n*HID + c] = acc;
        __syncthreads();
    }
}

// ------------------- per-layer node projection: fold residual, Pa/Pb -------------------
__global__ __launch_bounds__(256) void k_nodeA(const float* __restrict__ msg_w1,
                                               int l, int fold) {
    __shared__ float Ws[128*MH];   // rows 0..127 of msg_w1[l], 16KB
    __shared__ float hs[4][HID];
    int t = threadIdx.x;
    const float* W = msg_w1 + l*129*MH;
    for (int i = t; i < 128*MH; i += 256) Ws[i] = W[i];
    int ni = t >> 6, c = t & 63;
    int col = c & 31;
    const float* Wb = &Ws[(c < HID/2 ? 0 : HID)* (MH/ (MH/32)) ]; // placeholder fixed below
    (void)Wb;
    for (int node0 = blockIdx.x*4; node0 < NN; node0 += gridDim.x*4) {
        int n = node0 + ni;
        float hv = g_h[n*HID + c];
        if (fold) {
            hv = fmaf(g_c4[c], g_y4[n*HID + c], hv) + g_c4[64 + c];
            g_h[n*HID + c] = hv;
        }
        hs[ni][c] = hv;
        __syncthreads();
        const float* Wcol = &Ws[(c < 32 ? 0 : 64)*MH + col];
        float acc = 0.f;
        const float* hrow = hs[ni];
        #pragma unroll
        for (int k = 0; k < HID; k++) acc = fmaf(hrow[k], Wcol[k*MH], acc);
        if (c < 32) g_Pa[n*MH + col] = acc;
        else        g_Pb[n*MH + col] = acc;
        __syncthreads();
    }
}

// ------------------- edge stats pass: Σ z1, Σ z1² over edges -------------------
__global__ __launch_bounds__(256) void k_edge_stats(const int* __restrict__ ei,
                                                    const float* __restrict__ eattr,
                                                    const float* __restrict__ msg_w1,
                                                    const float* __restrict__ msg_b1,
                                                    int l) {
    __shared__ float wc[MH], b1s[MH];
    __shared__ float sh[128];
    int t = threadIdx.x;
    if (t < MH) { wc[t]  = msg_w1[l*129*MH + 128*MH + t]; b1s[t] = msg_b1[l*MH + t]; }
    if (t < 128) sh[t] = 0.f;
    __syncthreads();
    int lane = t & 31;
    float accS = 0.f, accQ = 0.f;
    int stride = gridDim.x*blockDim.x;
    for (int e = blockIdx.x*blockDim.x + t; e < NE; e += stride) {
        int s = ei[e], d = ei[NE + e];
        float ea = eattr[e];
        const float4* pa = reinterpret_cast<const float4*>(g_Pa + d*MH);
        const float4* pb = reinterpret_cast<const float4*>(g_Pb + s*MH);
        #pragma unroll
        for (int i = 0; i < 8; i++) {
            float4 A = pa[i], B = pb[i];
            float zv[4];
            int c0 = 4*i;
            zv[0] = A.x + B.x + fmaf(ea, wc[c0+0], b1s[c0+0]);
            zv[1] = A.y + B.y + fmaf(ea, wc[c0+1], b1s[c0+1]);
            zv[2] = A.z + B.z + fmaf(ea, wc[c0+2], b1s[c0+2]);
            zv[3] = A.w + B.w + fmaf(ea, wc[c0+3], b1s[c0+3]);
            #pragma unroll
            for (int j = 0; j < 4; j++) {
                float v = zv[j], s1 = v, s2 = v*v;
                #pragma unroll
                for (int o = 16; o; o >>= 1) {
                    s1 += __shfl_xor_sync(0xffffffffu, s1, o);
                    s2 += __shfl_xor_sync(0xffffffffu, s2, o);
                }
                int c = c0 + j;
                if (lane == c) { accS += s1; accQ += s2; }
            }
        }
    }
    atomicAdd(&sh[lane], accS);
    atomicAdd(&sh[64 + lane], accQ);
    __syncthreads();
    if (t < 128) atomicAdd(&g_stats[t], sh[t]);
}

// ------------------- BN constants (and zero stats for next stage) -------------------
__global__ void k_consts(const float* __restrict__ gamma, const float* __restrict__ beta,
                         float inv, int nch, int which) {
    int t = threadIdx.x; // 128
    float* out = (which == 0) ? g_c1 : (which == 1) ? g_c2 : (which == 2) ? g_c3 : g_c4;
    float a = 0.f, c = 0.f;
    if (t < nch) {
        float mu  = g_stats[t] * inv;
        float var = g_stats[64 + t] * inv - mu*mu;
        a = gamma[t] * rsqrtf(var + EPSB);
        c = beta[t] - a*mu;
    }
    __syncthreads();
    if (t < nch) { out[t] = a; out[64 + t] = c; }
    g_stats[t] = 0.f;
}

// ------------------- edge main pass: BN1+ReLU, @W2, ReLU, scatter, stats -------------------
__global__ __launch_bounds__(256) void k_edge_main(const int* __restrict__ ei,
                                                   const float* __restrict__ eattr,
                                                   const float* __restrict__ msg_w1,
                                                   const float* __restrict__ msg_b1,
                                                   const float* __restrict__ msg_w2,
                                                   const float* __restrict__ msg_b2,
                                                   int l) {
    __shared__ float Wt[HID*MH];   // Wt[c*32+k] = W2[k][c], 8KB
    __shared__ float b2s[HID], wc[MH], b1s[MH], a1s[MH], c1s[MH];
    __shared__ float sh[128];
    int t = threadIdx.x;
    const float* W2 = msg_w2 + l*MH*HID;
    for (int i = t; i < MH*HID; i += 256) { int k = i / HID, c = i % HID; Wt[c*MH + k] = W2[i]; }
    if (t < HID) b2s[t] = msg_b2[l*HID + t];
    if (t < MH) {
        wc[t]  = msg_w1[l*129*MH + 128*MH + t];
        b1s[t] = msg_b1[l*MH + t];
        a1s[t] = g_c1[t];
        c1s[t] = g_c1[64 + t];
    }
    if (t < 128) sh[t] = 0.f;
    __syncthreads();
    int lane = t & 31;
    float aS0 = 0.f, aQ0 = 0.f, aS1 = 0.f, aQ1 = 0.f;
    int stride = gridDim.x*blockDim.x;
    for (int e = blockIdx.x*blockDim.x + t; e < NE; e += stride) {
        int s = ei[e], d = ei[NE + e];
        float ea = eattr[e];
        float m[MH];
        const float4* pa = reinterpret_cast<const float4*>(g_Pa + d*MH);
        const float4* pb = reinterpret_cast<const float4*>(g_Pb + s*MH);
        #pragma unroll
        for (int i = 0; i < 8; i++) {
            float4 A = pa[i], B = pb[i];
            int c0 = 4*i;
            float z;
            z = A.x + B.x + fmaf(ea, wc[c0+0], b1s[c0+0]); m[c0+0] = fmaxf(fmaf(a1s[c0+0], z, c1s[c0+0]), 0.f);
            z = A.y + B.y + fmaf(ea, wc[c0+1], b1s[c0+1]); m[c0+1] = fmaxf(fmaf(a1s[c0+1], z, c1s[c0+1]), 0.f);
            z = A.z + B.z + fmaf(ea, wc[c0+2], b1s[c0+2]); m[c0+2] = fmaxf(fmaf(a1s[c0+2], z, c1s[c0+2]), 0.f);
            z = A.w + B.w + fmaf(ea, wc[c0+3], b1s[c0+3]); m[c0+3] = fmaxf(fmaf(a1s[c0+3], z, c1s[c0+3]), 0.f);
        }
        float* nrow = g_nsum + d*HID;
        #pragma unroll
        for (int c = 0; c < HID; c++) {
            const float4* w4 = reinterpret_cast<const float4*>(Wt + c*MH);
            float acc = b2s[c];
            #pragma unroll
            for (int i = 0; i < 8; i++) {
                float4 w = w4[i];
                acc = fmaf(m[4*i+0], w.x, acc);
                acc = fmaf(m[4*i+1], w.y, acc);
                acc = fmaf(m[4*i+2], w.z, acc);
                acc = fmaf(m[4*i+3], w.w, acc);
            }
            float y = fmaxf(acc, 0.f);
            atomicAdd(nrow + c, y);
            float s1 = y, s2 = y*y;
            #pragma unroll
            for (int o = 16; o; o >>= 1) {
                s1 += __shfl_xor_sync(0xffffffffu, s1, o);
                s2 += __shfl_xor_sync(0xffffffffu, s2, o);
            }
            if (lane == (c & 31)) {
                if (c < MH) { aS0 += s1; aQ0 += s2; }
                else        { aS1 += s1; aQ1 += s2; }
            }
        }
    }
    atomicAdd(&sh[lane],       aS0);
    atomicAdd(&sh[64 + lane],  aQ0);
    atomicAdd(&sh[32 + lane],  aS1);
    atomicAdd(&sh[96 + lane],  aQ1);
    __syncthreads();
    if (t < 128) atomicAdd(&g_stats[t], sh[t]);
}

// ------------------- update pass 1: agg from nsum/deg, z3 = [h,agg]@U1 + b, stats -------------------
__global__ __launch_bounds__(256) void k_update1(const float* __restrict__ upd_w1,
                                                 const float* __restrict__ upd_b1,
                                                 int l) {
    __shared__ float U1s[128*MH];  // 16KB
    __shared__ float rows[8*128];  // 4KB: [h(64), agg(64)] per node
    __shared__ float a2s[HID], c2s[HID], b3s[MH];
    __shared__ float sh[128];
    int t = threadIdx.x;
    const float* U1 = upd_w1 + l*128*MH;
    for (int i = t; i < 128*MH; i += 256) U1s[i] = U1[i];
    if (t < HID) { a2s[t] = g_c2[t]; c2s[t] = g_c2[64 + t]; }
    if (t < MH)  b3s[t] = upd_b1[l*MH + t];
    if (t < 128) sh[t] = 0.f;
    __syncthreads();
    int ni = t >> 5, j = t & 31;
    float accS = 0.f, accQ = 0.f;
    for (int node0 = blockIdx.x*8; node0 < NN; node0 += gridDim.x*8) {
        for (int idx = t; idx < 8*128; idx += 256) {
            int ni2 = idx >> 7, k = idx & 127;
            int n2 = node0 + ni2;
            float v;
            if (k < HID) v = g_h[n2*HID + k];
            else {
                int c = k - HID;
                v = fmaf(a2s[c], g_nsum[n2*HID + c], c2s[c]*g_deg[n2]);
            }
            rows[idx] = v;
        }
        __syncthreads();
        int n = node0 + ni;
        float acc = b3s[j];
        const float4* r4 = reinterpret_cast<const float4*>(rows + ni*128);
        #pragma unroll
        for (int k4 = 0; k4 < 32; k4++) {
            float4 r = r4[k4];
            acc = fmaf(r.x, U1s[(4*k4+0)*MH + j], acc);
            acc = fmaf(r.y, U1s[(4*k4+1)*MH + j], acc);
            acc = fmaf(r.z, U1s[(4*k4+2)*MH + j], acc);
            acc = fmaf(r.w, U1s[(4*k4+3)*MH + j], acc);
        }
        g_z3[n*MH + j] = acc;
        accS += acc; accQ += acc*acc;
        __syncthreads();
    }
    atomicAdd(&sh[j], accS);
    atomicAdd(&sh[64 + j], accQ);
    __syncthreads();
    if (t < 128) atomicAdd(&g_stats[t], sh[t]);
}

// ------------------- update pass 2: m3 = relu(a3*z3+c3), y4 = relu(m3@U2+b), stats -------------------
__global__ __launch_bounds__(256) void k_update2(const float* __restrict__ upd_w2,
                                                 const float* __restrict__ upd_b2,
                                                 int l) {
    __shared__ float U2s[MH*HID];  // 8KB
    __shared__ float m3s[4*MH];
    __shared__ float a3s[MH], c3s[MH], b4s[HID];
    __shared__ float sh[128];
    int t = threadIdx.x;
    const float* U2 = upd_w2 + l*MH*HID;
    for (int i = t; i < MH*HID; i += 256) U2s[i] = U2[i];
    if (t < MH) { a3s[t] = g_c3[t]; c3s[t] = g_c3[64 + t]; }
    if (t < HID) b4s[t] = upd_b2[l*HID + t];
    if (t < 128) sh[t] = 0.f;
    __syncthreads();
    int ni = t >> 6, c = t & 63;
    float accS = 0.f, accQ = 0.f;
    for (int node0 = blockIdx.x*4; node0 < NN; node0 += gridDim.x*4) {
        if (t < 4*MH) {
            int ni2 = t >> 5, k = t & 31;
            float z = g_z3[(node0 + ni2)*MH + k];
            m3s[t] = fmaxf(fmaf(a3s[k], z, c3s[k]), 0.f);
        }
        __syncthreads();
        int n = node0 + ni;
        float acc = b4s[c];
        const float* mr = m3s + ni*MH;
        #pragma unroll
        for (int k = 0; k < MH; k++) acc = fmaf(mr[k], U2s[k*HID + c], acc);
        float y = fmaxf(acc, 0.f);
        g_y4[n*HID + c] = y;
        accS += y; accQ += y*y;
        __syncthreads();
    }
    atomicAdd(&sh[c], accS);
    atomicAdd(&sh[64 + c], accQ);
    __syncthreads();
    if (t < 128) atomicAdd(&g_stats[t], sh[t]);
}

// ------------------- pooling (folds last residual) -------------------
__global__ __launch_bounds__(256) void k_pool(const int* __restrict__ batch) {
    int t = threadIdx.x;
    int node0 = blockIdx.x*4;
    int ni = t >> 6, c = t & 63;
    int n = node0 + ni;
    if (n >= NN) return;
    float hn = fmaf(g_c4[c], g_y4[n*HID + c], g_h[n*HID + c]) + g_c4[64 + c];
    int b = batch[n];
    atomicAdd(&g_pool[b*HID + c], hn);
    if (c == 0) atomicAdd(&g_pcnt[b], 1.0f);
}

__global__ void k_head(const float* __restrict__ out_w, const float* __restrict__ out_b,
                       float* __restrict__ out) {
    int g = blockIdx.x*blockDim.x + threadIdx.x;
    if (g >= NG) return;
    float acc = 0.f;
    #pragma unroll
    for (int k = 0; k < HID; k++) acc = fmaf(g_pool[g*HID + k], __ldg(&out_w[k]), acc);
    float cnt = fmaxf(g_pcnt[g], 1.0f);
    out[g] = fmaxf(acc / cnt + __ldg(&out_b[0]), 0.f);
}

// ------------------- launcher -------------------
extern "C" void kernel_launch(void* const* d_in, const int* in_sizes, int n_in,
                              void* d_out, int out_size) {
    const float* x        = (const float*)d_in[0];
    const int*   ei       = (const int*)  d_in[1];
    const float* eattr    = (const float*)d_in[2];
    const int*   batch    = (const int*)  d_in[3];
    const float* lin_in_w = (const float*)d_in[4];
    const float* lin_in_b = (const float*)d_in[5];
    const float* msg_w1   = (const float*)d_in[6];
    const float* msg_b1   = (const float*)d_in[7];
    const float* msg_g1   = (const float*)d_in[8];
    const float* msg_be1  = (const float*)d_in[9];
    const float* msg_w2   = (const float*)d_in[10];
    const float* msg_b2   = (const float*)d_in[11];
    const float* msg_g2   = (const float*)d_in[12];
    const float* msg_be2  = (const float*)d_in[13];
    const float* upd_w1   = (const float*)d_in[14];
    const float* upd_b1   = (const float*)d_in[15];
    const float* upd_g1   = (const float*)d_in[16];
    const float* upd_be1  = (const float*)d_in[17];
    const float* upd_w2   = (const float*)d_in[18];
    const float* upd_b2   = (const float*)d_in[19];
    const float* upd_g2   = (const float*)d_in[20];
    const float* upd_be2  = (const float*)d_in[21];
    const float* out_w    = (const float*)d_in[22];
    const float* out_b    = (const float*)d_in[23];
    float* out = (float*)d_out;

    k_prep<<<(NN + 255)/256, 256>>>();
    k_deg<<<NE/256, 256>>>(ei);
    k_init<<<GRID_P, 256>>>(x, lin_in_w, lin_in_b);

    const float invE = 1.0f / (float)NE;
    const float invN = 1.0f / (float)NN;

    for (int l = 0; l < NL; l++) {
        k_nodeA<<<GRID_P, 256>>>(msg_w1, l, l > 0 ? 1 : 0);
        k_edge_stats<<<GRID_P, 256>>>(ei, eattr, msg_w1, msg_b1, l);
        k_consts<<<1, 128>>>(msg_g1 + l*MH, msg_be1 + l*MH, invE, MH, 0);
        k_zero_nsum<<<(NN*HID/4 + 255)/256, 256>>>();
        k_edge_main<<<GRID_P, 256>>>(ei, eattr, msg_w1, msg_b1, msg_w2, msg_b2, l);
        k_consts<<<1, 128>>>(msg_g2 + l*HID, msg_be2 + l*HID, invE, HID, 1);
        k_update1<<<GRID_P, 256>>>(upd_w1, upd_b1, l);
        k_consts<<<1, 128>>>(upd_g1 + l*MH, upd_be1 + l*MH, invN, MH, 2);
        k_update2<<<GRID_P, 256>>>(upd_w2, upd_b2, l);
        k_consts<<<1, 128>>>(upd_g2 + l*HID, upd_be2 + l*HID, invN, HID, 3);
    }

    k_pool<<<NN/4, 256>>>(batch);
    k_head<<<2, 256>>>(out_w, out_b, out);
}

// round 2
// speedup vs baseline: 1.6242x; 1.6242x over previous
#include <cuda_runtime.h>

#define NN 100000
#define NE 800000
#define NG 512
#define IND 16
#define HID 64
#define MH  32
#define NL  3
#define EPSB 1e-5f
#define NTILE (NE/32)   // 25000 edge tiles of 32

#define GRID_P 1184   // 8 blocks per SM (148 SMs)

// ------------------- f32x2 packed helpers -------------------
__device__ __forceinline__ unsigned long long pk2(float lo, float hi) {
    unsigned long long r;
    asm("mov.b64 %0,{%1,%2};" : "=l"(r) : "f"(lo), "f"(hi));
    return r;
}
__device__ __forceinline__ void upk2(unsigned long long v, float& lo, float& hi) {
    asm("mov.b64 {%0,%1},%2;" : "=f"(lo), "=f"(hi) : "l"(v));
}
__device__ __forceinline__ unsigned long long f2fma(unsigned long long a,
                                                    unsigned long long b,
                                                    unsigned long long c) {
    unsigned long long r;
    asm("fma.rn.f32x2 %0,%1,%2,%3;" : "=l"(r) : "l"(a), "l"(b), "l"(c));
    return r;
}

// ------------------- scratch (static device memory; no allocs) -------------------
__device__ float g_h[NN*HID];
__device__ float g_Pa[NN*MH];
__device__ float g_Pb[NN*MH];
__device__ float g_nsum[NN*HID];
__device__ float g_z3[NN*MH];
__device__ float g_y4[NN*HID];
__device__ float g_deg[NN];
__device__ float g_stats[128];     // [0..63] sum per channel, [64..127] sumsq
__device__ float g_c1[128];        // a in [0..63], c in [64..127]
__device__ float g_c2[128];
__device__ float g_c3[128];
__device__ float g_c4[128];        // fold constants for residual (BN4)
__device__ float g_pool[NG*HID];
__device__ float g_pcnt[NG];

// ------------------- prep: zero deg/pool/pcnt/stats -------------------
__global__ void k_prep() {
    int i = blockIdx.x*blockDim.x + threadIdx.x;
    if (i < NN)        g_deg[i]  = 0.f;
    if (i < NG*HID)    g_pool[i] = 0.f;
    if (i < NG)        g_pcnt[i] = 0.f;
    if (i < 128)       g_stats[i] = 0.f;
}

__global__ void k_deg(const int* __restrict__ ei) {
    int e = blockIdx.x*blockDim.x + threadIdx.x;
    if (e < NE) atomicAdd(&g_deg[ei[NE + e]], 1.0f);
}

__global__ void k_zero_nsum() {
    int i = blockIdx.x*blockDim.x + threadIdx.x;   // NN*HID/4 float4
    if (i < NN*HID/4) reinterpret_cast<float4*>(g_nsum)[i] = make_float4(0.f,0.f,0.f,0.f);
}

// ------------------- input projection: h = x @ Win + b -------------------
__global__ __launch_bounds__(256) void k_init(const float* __restrict__ x,
                                              const float* __restrict__ w,
                                              const float* __restrict__ b) {
    __shared__ float Ws[IND*HID];
    __shared__ float bs[HID];
    __shared__ float xs[4][IND];
    int t = threadIdx.x;
    for (int i = t; i < IND*HID; i += 256) Ws[i] = w[i];
    if (t < HID) bs[t] = b[t];
    int ni = t >> 6, c = t & 63;
    for (int node0 = blockIdx.x*4; node0 < NN; node0 += gridDim.x*4) {
        if (t < 4*IND) xs[t/IND][t%IND] = x[(node0 + t/IND)*IND + (t%IND)];
        __syncthreads();
        int n = node0 + ni;
        float acc = bs[c];
        #pragma unroll
        for (int k = 0; k < IND; k++) acc = fmaf(xs[ni][k], Ws[k*HID + c], acc);
        g_h[n*HID + c] = acc;
        __syncthreads();
    }
}

// ------------------- per-layer node projection: fold residual, Pa/Pb -------------------
// W column held in registers (packed pairs); h row broadcast from smem.
__global__ __launch_bounds__(256) void k_nodeA(const float* __restrict__ msg_w1,
                                               int l, int fold) {
    __shared__ float hs[4][HID];
    int t = threadIdx.x;
    int ni = t >> 6, c = t & 63, col = c & 31;
    const float* W = msg_w1 + l*129*MH + ((c < 32) ? 0 : 64)*MH + col;
    unsigned long long Wp[32];
    #pragma unroll
    for (int kk = 0; kk < 32; kk++)
        Wp[kk] = pk2(W[(2*kk)*MH], W[(2*kk+1)*MH]);
    float a4 = 0.f, c4 = 0.f;
    if (fold) { a4 = g_c4[c]; c4 = g_c4[64 + c]; }
    for (int node0 = blockIdx.x*4; node0 < NN; node0 += gridDim.x*4) {
        int n = node0 + ni;
        float hv = g_h[n*HID + c];
        if (fold) {
            hv = fmaf(a4, g_y4[n*HID + c], hv) + c4;
            g_h[n*HID + c] = hv;
        }
        hs[ni][c] = hv;
        __syncthreads();
        const unsigned long long* hp = reinterpret_cast<const unsigned long long*>(hs[ni]);
        unsigned long long acc = 0ULL;
        #pragma unroll
        for (int kk = 0; kk < 32; kk++) acc = f2fma(hp[kk], Wp[kk], acc);
        float lo, hi; upk2(acc, lo, hi);
        if (c < 32) g_Pa[n*MH + col] = lo + hi;
        else        g_Pb[n*MH + col] = lo + hi;
        __syncthreads();
    }
}

// ------------------- edge stats pass (warp-transposed): Σ z1, Σ z1² -------------------
__global__ __launch_bounds__(256) void k_edge_stats(const int* __restrict__ ei,
                                                    const float* __restrict__ eattr,
                                                    const float* __restrict__ msg_w1,
                                                    const float* __restrict__ msg_b1,
                                                    int l) {
    __shared__ float zs[8][32*34];
    __shared__ float wcs[MH], b1s[MH];
    __shared__ float sh[128];
    int t = threadIdx.x, wq = t >> 5, lane = t & 31;
    if (t < MH) { wcs[t] = msg_w1[l*129*MH + 128*MH + t]; b1s[t] = msg_b1[l*MH + t]; }
    if (t < 128) sh[t] = 0.f;
    __syncthreads();
    float sS = 0.f, sQ = 0.f;
    for (int tile = blockIdx.x*8 + wq; tile < NTILE; tile += gridDim.x*8) {
        int e = tile*32 + lane;
        int s = ei[e], d = ei[NE + e];
        float ea = eattr[e];
        const float4* pa = reinterpret_cast<const float4*>(g_Pa + d*MH);
        const float4* pb = reinterpret_cast<const float4*>(g_Pb + s*MH);
        float* zr = &zs[wq][lane*34];
        #pragma unroll
        for (int i = 0; i < 8; i++) {
            float4 A = pa[i], B = pb[i]; int c0 = 4*i;
            zr[c0+0] = A.x + B.x + fmaf(ea, wcs[c0+0], b1s[c0+0]);
            zr[c0+1] = A.y + B.y + fmaf(ea, wcs[c0+1], b1s[c0+1]);
            zr[c0+2] = A.z + B.z + fmaf(ea, wcs[c0+2], b1s[c0+2]);
            zr[c0+3] = A.w + B.w + fmaf(ea, wcs[c0+3], b1s[c0+3]);
        }
        __syncwarp();
        #pragma unroll 8
        for (int e2 = 0; e2 < 32; e2++) {
            float v = zs[wq][e2*34 + lane];   // conflict-free: bank = (2*e2+lane)&31
            sS += v; sQ = fmaf(v, v, sQ);
        }
        __syncwarp();
    }
    atomicAdd(&sh[lane], sS);
    atomicAdd(&sh[64 + lane], sQ);
    __syncthreads();
    if (t < 128) atomicAdd(&g_stats[t], sh[t]);
}

// ------------------- BN constants (and zero stats for next stage) -------------------
__global__ void k_consts(const float* __restrict__ gamma, const float* __restrict__ beta,
                         float inv, int nch, int which) {
    int t = threadIdx.x; // 128
    float* out = (which == 0) ? g_c1 : (which == 1) ? g_c2 : (which == 2) ? g_c3 : g_c4;
    float a = 0.f, c = 0.f;
    if (t < nch) {
        float mu  = g_stats[t] * inv;
        float var = g_stats[64 + t] * inv - mu*mu;
        a = gamma[t] * rsqrtf(var + EPSB);
        c = beta[t] - a*mu;
    }
    __syncthreads();
    if (t < nch) { out[t] = a; out[64 + t] = c; }
    g_stats[t] = 0.f;
}

// ------------------- edge main pass (warp-transposed): BN1+ReLU, @W2, ReLU, scatter, stats
__global__ __launch_bounds__(256) void k_edge_main(const int* __restrict__ ei,
                                                   const float* __restrict__ eattr,
                                                   const float* __restrict__ msg_w1,
                                                   const float* __restrict__ msg_b1,
                                                   const float* __restrict__ msg_w2,
                                                   const float* __restrict__ msg_b2,
                                                   int l) {
    __shared__ float m_s[8][32*34];
    __shared__ int   d_s[8][32];
    __shared__ float a1s[MH], wps[MH], bps[MH];   // folded BN1: m = relu(a1*(A+B) + ea*wps + bps)
    __shared__ float sh[128];
    int t = threadIdx.x, wq = t >> 5, lane = t & 31;
    const float* W2 = msg_w2 + l*MH*HID;
    if (t < MH) {
        float a1 = g_c1[t], c1 = g_c1[64 + t];
        a1s[t] = a1;
        wps[t] = a1 * msg_w1[l*129*MH + 128*MH + t];
        bps[t] = fmaf(a1, msg_b1[l*MH + t], c1);
    }
    if (t < 128) sh[t] = 0.f;
    // per-lane weight columns (c = lane, c+32), packed over k pairs
    unsigned long long WA[16], WB[16];
    #pragma unroll
    for (int kk = 0; kk < 16; kk++) {
        WA[kk] = pk2(W2[(2*kk)*HID + lane],      W2[(2*kk+1)*HID + lane]);
        WB[kk] = pk2(W2[(2*kk)*HID + lane + 32], W2[(2*kk+1)*HID + lane + 32]);
    }
    float b2a = msg_b2[l*HID + lane], b2b = msg_b2[l*HID + lane + 32];
    __syncthreads();
    float sS0 = 0.f, sQ0 = 0.f, sS1 = 0.f, sQ1 = 0.f;
    for (int tile = blockIdx.x*8 + wq; tile < NTILE; tile += gridDim.x*8) {
        // ---- phase A: lane = edge within tile, compute message m[0..31] ----
        int e = tile*32 + lane;
        int s = ei[e], d = ei[NE + e];
        float ea = eattr[e];
        d_s[wq][lane] = d;
        const float4* pa = reinterpret_cast<const float4*>(g_Pa + d*MH);
        const float4* pb = reinterpret_cast<const float4*>(g_Pb + s*MH);
        float* mr = &m_s[wq][lane*34];
        #pragma unroll
        for (int i = 0; i < 8; i++) {
            float4 A = pa[i], B = pb[i]; int c0 = 4*i;
            mr[c0+0] = fmaxf(fmaf(a1s[c0+0], A.x + B.x, fmaf(ea, wps[c0+0], bps[c0+0])), 0.f);
            mr[c0+1] = fmaxf(fmaf(a1s[c0+1], A.y + B.y, fmaf(ea, wps[c0+1], bps[c0+1])), 0.f);
            mr[c0+2] = fmaxf(fmaf(a1s[c0+2], A.z + B.z, fmaf(ea, wps[c0+2], bps[c0+2])), 0.f);
            mr[c0+3] = fmaxf(fmaf(a1s[c0+3], A.w + B.w, fmaf(ea, wps[c0+3], bps[c0+3])), 0.f);
        }
        __syncwarp();
        // ---- phase B: lane = output channel pair (lane, lane+32) ----
        #pragma unroll 2
        for (int e2 = 0; e2 < 32; e2++) {
            const unsigned long long* mp =
                reinterpret_cast<const unsigned long long*>(&m_s[wq][e2*34]);
            unsigned long long accA = 0ULL, accB = 0ULL;
            #pragma unroll
            for (int kk = 0; kk < 16; kk++) {
                unsigned long long m2 = mp[kk];   // LDS.64 broadcast
                accA = f2fma(m2, WA[kk], accA);
                accB = f2fma(m2, WB[kk], accB);
            }
            float a0, a1v, b0, b1v;
            upk2(accA, a0, a1v); upk2(accB, b0, b1v);
            float y0 = fmaxf(a0 + a1v + b2a, 0.f);
            float y1 = fmaxf(b0 + b1v + b2b, 0.f);
            sS0 += y0; sQ0 = fmaf(y0, y0, sQ0);
            sS1 += y1; sQ1 = fmaf(y1, y1, sQ1);
            int dd = d_s[wq][e2];
            atomicAdd(&g_nsum[dd*HID + lane],      y0);   // coalesced across lanes
            atomicAdd(&g_nsum[dd*HID + lane + 32], y1);
        }
        __syncwarp();
    }
    atomicAdd(&sh[lane],      sS0);
    atomicAdd(&sh[64 + lane], sQ0);
    atomicAdd(&sh[32 + lane], sS1);
    atomicAdd(&sh[96 + lane], sQ1);
    __syncthreads();
    if (t < 128) atomicAdd(&g_stats[t], sh[t]);
}

// ------------------- update pass 1: agg fold, z3 = [h,agg]@U1 + b, stats -------------------
__global__ __launch_bounds__(256) void k_update1(const float* __restrict__ upd_w1,
                                                 const float* __restrict__ upd_b1,
                                                 int l) {
    __shared__ unsigned long long Wp[64*32];  // 16KB packed pairs: (U1[2kk][j],U1[2kk+1][j])
    __shared__ float rows[8*128];             // 4KB: [h(64), agg(64)] per node
    __shared__ float a2s[HID], c2s[HID];
    __shared__ float sh[128];
    int t = threadIdx.x;
    const float* U1 = upd_w1 + l*128*MH;
    for (int i = t; i < 64*32; i += 256) {
        int kk = i >> 5, j = i & 31;
        Wp[i] = pk2(U1[(2*kk)*MH + j], U1[(2*kk+1)*MH + j]);
    }
    if (t < HID) { a2s[t] = g_c2[t]; c2s[t] = g_c2[64 + t]; }
    if (t < 128) sh[t] = 0.f;
    __syncthreads();
    int ni = t >> 5, j = t & 31;
    float b3 = upd_b1[l*MH + j];
    float accS = 0.f, accQ = 0.f;
    for (int node0 = blockIdx.x*8; node0 < NN; node0 += gridDim.x*8) {
        for (int idx = t; idx < 8*128; idx += 256) {
            int ni2 = idx >> 7, k = idx & 127;
            int n2 = node0 + ni2;
            float v;
            if (k < HID) v = g_h[n2*HID + k];
            else {
                int cc = k - HID;
                v = fmaf(a2s[cc], g_nsum[n2*HID + cc], c2s[cc]*g_deg[n2]);
            }
            rows[idx] = v;
        }
        __syncthreads();
        int n = node0 + ni;
        const unsigned long long* rp =
            reinterpret_cast<const unsigned long long*>(rows + ni*128);
        unsigned long long acc = 0ULL;
        #pragma unroll
        for (int kk = 0; kk < 64; kk++) acc = f2fma(rp[kk], Wp[kk*32 + j], acc);
        float lo, hi; upk2(acc, lo, hi);
        float z = lo + hi + b3;
        g_z3[n*MH + j] = z;
        accS += z; accQ = fmaf(z, z, accQ);
        __syncthreads();
    }
    atomicAdd(&sh[j], accS);
    atomicAdd(&sh[64 + j], accQ);
    __syncthreads();
    if (t < 128) atomicAdd(&g_stats[t], sh[t]);
}

// ------------------- update pass 2: m3 = relu(a3*z3+c3), y4 = relu(m3@U2+b), stats -------
__global__ __launch_bounds__(256) void k_update2(const float* __restrict__ upd_w2,
                                                 const float* __restrict__ upd_b2,
                                                 int l) {
    __shared__ float m3s[4*MH];
    __shared__ float a3s[MH], c3s[MH];
    __shared__ float sh[128];
    int t = threadIdx.x, ni = t >> 6, c = t & 63;
    const float* U2 = upd_w2 + l*MH*HID;
    unsigned long long Up[16];
    #pragma unroll
    for (int kk = 0; kk < 16; kk++)
        Up[kk] = pk2(U2[(2*kk)*HID + c], U2[(2*kk+1)*HID + c]);
    if (t < MH) { a3s[t] = g_c3[t]; c3s[t] = g_c3[64 + t]; }
    if (t < 128) sh[t] = 0.f;
    float b4 = upd_b2[l*HID + c];
    __syncthreads();
    float accS = 0.f, accQ = 0.f;
    for (int node0 = blockIdx.x*4; node0 < NN; node0 += gridDim.x*4) {
        if (t < 4*MH) {
            int ni2 = t >> 5, k = t & 31;
            float z = g_z3[(node0 + ni2)*MH + k];
            m3s[t] = fmaxf(fmaf(a3s[k], z, c3s[k]), 0.f);
        }
        __syncthreads();
        int n = node0 + ni;
        const unsigned long long* mp =
            reinterpret_cast<const unsigned long long*>(m3s + ni*MH);
        unsigned long long acc = 0ULL;
        #pragma unroll
        for (int kk = 0; kk < 16; kk++) acc = f2fma(mp[kk], Up[kk], acc);
        float lo, hi; upk2(acc, lo, hi);
        float y = fmaxf(lo + hi + b4, 0.f);
        g_y4[n*HID + c] = y;
        accS += y; accQ = fmaf(y, y, accQ);
        __syncthreads();
    }
    atomicAdd(&sh[c], accS);
    atomicAdd(&sh[64 + c], accQ);
    __syncthreads();
    if (t < 128) atomicAdd(&g_stats[t], sh[t]);
}

// ------------------- pooling (folds last residual) -------------------
__global__ __launch_bounds__(256) void k_pool(const int* __restrict__ batch) {
    int t = threadIdx.x;
    int node0 = blockIdx.x*4;
    int ni = t >> 6, c = t & 63;
    int n = node0 + ni;
    if (n >= NN) return;
    float hn = fmaf(g_c4[c], g_y4[n*HID + c], g_h[n*HID + c]) + g_c4[64 + c];
    int b = batch[n];
    atomicAdd(&g_pool[b*HID + c], hn);
    if (c == 0) atomicAdd(&g_pcnt[b], 1.0f);
}

__global__ void k_head(const float* __restrict__ out_w, const float* __restrict__ out_b,
                       float* __restrict__ out) {
    int g = blockIdx.x*blockDim.x + threadIdx.x;
    if (g >= NG) return;
    float acc = 0.f;
    #pragma unroll
    for (int k = 0; k < HID; k++) acc = fmaf(g_pool[g*HID + k], __ldg(&out_w[k]), acc);
    float cnt = fmaxf(g_pcnt[g], 1.0f);
    out[g] = fmaxf(acc / cnt + __ldg(&out_b[0]), 0.f);
}

// ------------------- launcher -------------------
extern "C" void kernel_launch(void* const* d_in, const int* in_sizes, int n_in,
                              void* d_out, int out_size) {
    const float* x        = (const float*)d_in[0];
    const int*   ei       = (const int*)  d_in[1];
    const float* eattr    = (const float*)d_in[2];
    const int*   batch    = (const int*)  d_in[3];
    const float* lin_in_w = (const float*)d_in[4];
    const float* lin_in_b = (const float*)d_in[5];
    const float* msg_w1   = (const float*)d_in[6];
    const float* msg_b1   = (const float*)d_in[7];
    const float* msg_g1   = (const float*)d_in[8];
    const float* msg_be1  = (const float*)d_in[9];
    const float* msg_w2   = (const float*)d_in[10];
    const float* msg_b2   = (const float*)d_in[11];
    const float* msg_g2   = (const float*)d_in[12];
    const float* msg_be2  = (const float*)d_in[13];
    const float* upd_w1   = (const float*)d_in[14];
    const float* upd_b1   = (const float*)d_in[15];
    const float* upd_g1   = (const float*)d_in[16];
    const float* upd_be1  = (const float*)d_in[17];
    const float* upd_w2   = (const float*)d_in[18];
    const float* upd_b2   = (const float*)d_in[19];
    const float* upd_g2   = (const float*)d_in[20];
    const float* upd_be2  = (const float*)d_in[21];
    const float* out_w    = (const float*)d_in[22];
    const float* out_b    = (const float*)d_in[23];
    float* out = (float*)d_out;

    k_prep<<<(NN + 255)/256, 256>>>();
    k_deg<<<NE/256, 256>>>(ei);
    k_init<<<GRID_P, 256>>>(x, lin_in_w, lin_in_b);

    const float invE = 1.0f / (float)NE;
    const float invN = 1.0f / (float)NN;

    for (int l = 0; l < NL; l++) {
        k_nodeA<<<GRID_P, 256>>>(msg_w1, l, l > 0 ? 1 : 0);
        k_zero_nsum<<<(NN*HID/4 + 255)/256, 256>>>();
        k_edge_stats<<<GRID_P, 256>>>(ei, eattr, msg_w1, msg_b1, l);
        k_consts<<<1, 128>>>(msg_g1 + l*MH, msg_be1 + l*MH, invE, MH, 0);
        k_edge_main<<<GRID_P, 256>>>(ei, eattr, msg_w1, msg_b1, msg_w2, msg_b2, l);
        k_consts<<<1, 128>>>(msg_g2 + l*HID, msg_be2 + l*HID, invE, HID, 1);
        k_update1<<<GRID_P, 256>>>(upd_w1, upd_b1, l);
        k_consts<<<1, 128>>>(upd_g1 + l*MH, upd_be1 + l*MH, invN, MH, 2);
        k_update2<<<GRID_P, 256>>>(upd_w2, upd_b2, l);
        k_consts<<<1, 128>>>(upd_g2 + l*HID, upd_be2 + l*HID, invN, HID, 3);
    }

    k_pool<<<NN/4, 256>>>(batch);
    k_head<<<2, 256>>>(out_w, out_b, out);
}